// round 16
// baseline (speedup 1.0000x reference)
#include <cuda_runtime.h>
#include <cuda_fp16.h>
#include <math.h>
#include <stdint.h>

// Shapes
#define BB 128      // batch
#define SS 64       // seq
#define UU 512      // units
#define VV 32000    // vocab
#define MM1 (BB*SS) // 8192 rows for the attention GEMM

// async pipeline tile geometry: BM=64, BN=128, BK=32; 256 threads
#define AS2 80                      // A row stride bytes (64B fp16 data + 16 pad)
#define BS2 272                     // B row stride bytes (256B fp16 data + 16 pad)
#define STG_A (64 * AS2)            // 5120
#define STG_B (32 * BS2)            // 8704
#define STG   (STG_A + STG_B)       // 13824

// -------------------- scratch (no allocations allowed) --------------------
__device__ float  g_spart[4 * MM1];           // score partial sums (4 N-slices)
__device__ __half g_xc_h[BB * 2 * UU];        // [x | context] fp16
__device__ float  g_gpart[4 * BB * 3 * UU];   // GRU gates split-K partials
__device__ float  g_ypart[4 * BB * UU];       // dense split-K partials
__device__ __half g_state_h[BB * UU];         // GRU state fp16 (dense A operand)
__device__ __half g_y_h[BB * UU];             // dense output fp16 (logits A operand)
__device__ __half g_attn_h[MM1 * UU];         // fp16 attn
__device__ __half g_W0_h[UU * UU];            // fp16 W0  [k][n]
__device__ __half g_gruk_h[2 * UU * 3 * UU];  // fp16 gru_k [k][n]
__device__ __half g_dW_h[UU * UU];            // fp16 dW [k][n]
__device__ __half g_oW_h[(size_t)UU * VV];    // fp16 oW [k][v]

// -------------------- helpers --------------------
__device__ __forceinline__ uint32_t packh2(float lo, float hi) {
    half2 h = __floats2half2_rn(lo, hi);
    return *reinterpret_cast<uint32_t*>(&h);
}

__device__ __forceinline__ void mma_f16(float c[4],
                                        uint32_t a0, uint32_t a1, uint32_t a2, uint32_t a3,
                                        uint32_t b0, uint32_t b1) {
    asm volatile(
        "mma.sync.aligned.m16n8k16.row.col.f32.f16.f16.f32 "
        "{%0,%1,%2,%3}, {%4,%5,%6,%7}, {%8,%9}, {%0,%1,%2,%3};"
        : "+f"(c[0]), "+f"(c[1]), "+f"(c[2]), "+f"(c[3])
        : "r"(a0), "r"(a1), "r"(a2), "r"(a3), "r"(b0), "r"(b1));
}

__device__ __forceinline__ void ldsm4(uint32_t& r0, uint32_t& r1, uint32_t& r2, uint32_t& r3,
                                      uint32_t addr) {
    asm volatile("ldmatrix.sync.aligned.m8n8.x4.shared.b16 {%0,%1,%2,%3}, [%4];"
                 : "=r"(r0), "=r"(r1), "=r"(r2), "=r"(r3) : "r"(addr));
}
__device__ __forceinline__ void ldsm4t(uint32_t& r0, uint32_t& r1, uint32_t& r2, uint32_t& r3,
                                       uint32_t addr) {
    asm volatile("ldmatrix.sync.aligned.m8n8.x4.trans.shared.b16 {%0,%1,%2,%3}, [%4];"
                 : "=r"(r0), "=r"(r1), "=r"(r2), "=r"(r3) : "r"(addr));
}

__device__ __forceinline__ void cp_async16(uint32_t dst, const void* src) {
    asm volatile("cp.async.cg.shared.global [%0], [%1], 16;" :: "r"(dst), "l"(src));
}
__device__ __forceinline__ void cp_commit() {
    asm volatile("cp.async.commit_group;" ::: "memory");
}
template<int N> __device__ __forceinline__ void cp_wait() {
    asm volatile("cp.async.wait_group %0;" :: "n"(N) : "memory");
}

// issue one 64x32 A tile + 32x128 B tile into a pipeline slot (256 threads)
__device__ __forceinline__ void issue_t(uint32_t sbase, uint32_t slotOff,
                                        const __half* __restrict__ Ah, int mbase, int lda,
                                        const __half* __restrict__ Bh, int nbase, int ldb,
                                        int kb, int tid) {
    uint32_t sA = sbase + slotOff;
    uint32_t sB = sA + STG_A;
    int arow = tid >> 2, apart = tid & 3;
    cp_async16(sA + arow * AS2 + apart * 16,
               Ah + (size_t)(mbase + arow) * lda + kb + apart * 8);
    #pragma unroll
    for (int it = 0; it < 2; it++) {
        int i = tid + it * 256;
        int row = i >> 4, part = i & 15;
        cp_async16(sB + row * BS2 + part * 16,
                   Bh + (size_t)(kb + row) * ldb + nbase + part * 8);
    }
    cp_commit();
}

// fragment compute over one staged tile; warp (wm,wn) handles 32x32 region
__device__ __forceinline__ void mma_tile(float (&acc)[2][4][4], uint32_t aA, uint32_t aB) {
    #pragma unroll
    for (int ks = 0; ks < 2; ks++) {
        uint32_t a[2][4], b[2][4];
        #pragma unroll
        for (int mt = 0; mt < 2; mt++)
            ldsm4(a[mt][0], a[mt][1], a[mt][2], a[mt][3],
                  aA + mt * 16 * AS2 + ks * 32);
        #pragma unroll
        for (int ng = 0; ng < 2; ng++)
            ldsm4t(b[ng][0], b[ng][1], b[ng][2], b[ng][3],
                   aB + ng * 32 + ks * 16 * BS2);
        #pragma unroll
        for (int mt = 0; mt < 2; mt++)
            #pragma unroll
            for (int nt = 0; nt < 4; nt++) {
                int ng = nt >> 1, lo = (nt & 1) * 2;
                mma_f16(acc[mt][nt], a[mt][0], a[mt][1], a[mt][2], a[mt][3],
                        b[ng][lo], b[ng][lo + 1]);
            }
    }
}

// ============================================================
// fp32 -> fp16 conversions (full grid; they are bandwidth machines)
// ============================================================
__global__ __launch_bounds__(256)
void f2h_dual(const float* __restrict__ sa, __half* __restrict__ da, int n8a,
              const float* __restrict__ sb, __half* __restrict__ db, int n8b) {
    int i = blockIdx.x * blockDim.x + threadIdx.x;
    const float4* s4;
    uint4* d4;
    int j;
    if (i < n8a) { s4 = reinterpret_cast<const float4*>(sa); d4 = reinterpret_cast<uint4*>(da); j = i; }
    else { j = i - n8a; if (j >= n8b) return;
           s4 = reinterpret_cast<const float4*>(sb); d4 = reinterpret_cast<uint4*>(db); }
    float4 a = s4[2 * j], b = s4[2 * j + 1];
    uint4 o;
    o.x = packh2(a.x, a.y); o.y = packh2(a.z, a.w);
    o.z = packh2(b.x, b.y); o.w = packh2(b.z, b.w);
    d4[j] = o;
}
// column-range conversion: convert cols [c0, c0 + ncols8*8) of a [UU][ld] matrix
__global__ __launch_bounds__(256)
void f2h_cols(const float* __restrict__ src, __half* __restrict__ dst,
              int ld, int c0, int ncols8) {
    int i = blockIdx.x * blockDim.x + threadIdx.x;
    int total = UU * ncols8;
    if (i >= total) return;
    int k = i / ncols8, c8 = i % ncols8;
    const float4* s4 = reinterpret_cast<const float4*>(src + (size_t)k * ld + c0 + c8 * 8);
    float4 a = s4[0], b = s4[1];
    uint4 o;
    o.x = packh2(a.x, a.y); o.y = packh2(a.z, a.w);
    o.z = packh2(b.x, b.y); o.w = packh2(b.z, b.w);
    *reinterpret_cast<uint4*>(dst + (size_t)k * ld + c0 + c8 * 8) = o;
}

// ============================================================
// Kernel 1: score partials. NSTG=4, forced 3 blocks/SM. grid (128, 4).
// ============================================================
__global__ __launch_bounds__(256, 3)
void score_async(const __half* __restrict__ Ah, const __half* __restrict__ Bh,
                 const float* __restrict__ b0, const float* __restrict__ b1,
                 const float* __restrict__ vW) {
    extern __shared__ char smem[];
    float (*sred)[4] = reinterpret_cast<float (*)[4]>(smem + 4 * STG);

    const int tid = threadIdx.x;
    const int warp = tid >> 5, lane = tid & 31;
    const int wm = warp >> 2, wn = warp & 3;
    const int g = lane >> 2, tg = lane & 3;
    const int mbase = blockIdx.x * 64;
    const int nbase = blockIdx.y * 128;

    const uint32_t sbase = (uint32_t)__cvta_generic_to_shared(smem);
    const int sub = lane >> 3, li = lane & 7;
    const int ao = wm * 32 * AS2 + ((sub & 1) * 8 + li) * AS2 + (sub >> 1) * 16;
    const int bo = wn * 64 + ((sub & 1) * 8 + li) * BS2 + (sub >> 1) * 16;

    float acc[2][4][4];
    #pragma unroll
    for (int mt = 0; mt < 2; mt++)
        #pragma unroll
        for (int nt = 0; nt < 4; nt++)
            #pragma unroll
            for (int q = 0; q < 4; q++) acc[mt][nt][q] = 0.f;

    const int T = UU / 32;  // 16
    issue_t(sbase, 0 * STG, Ah, mbase, UU, Bh, nbase, UU, 0, tid);
    issue_t(sbase, 1 * STG, Ah, mbase, UU, Bh, nbase, UU, 32, tid);
    issue_t(sbase, 2 * STG, Ah, mbase, UU, Bh, nbase, UU, 64, tid);

    for (int t = 0; t < T; t++) {
        cp_wait<2>();
        __syncthreads();
        uint32_t so = (uint32_t)(t & 3) * STG;
        mma_tile(acc, sbase + so + ao, sbase + so + STG_A + bo);
        if (t + 3 < T)
            issue_t(sbase, (uint32_t)((t + 3) & 3) * STG, Ah, mbase, UU, Bh, nbase, UU,
                    (t + 3) * 32, tid);
        else
            cp_commit();
    }

    // fused epilogue: tanh(+bias) * vW -> per-row partial sums
    float rs[2][2] = {{0.f, 0.f}, {0.f, 0.f}};
    #pragma unroll
    for (int ng = 0; ng < 2; ng++)
        #pragma unroll
        for (int j = 0; j < 2; j++) {
            int col = nbase + wn * 32 + ng * 16 + j * 8 + 2 * tg;
            float bia0 = b0[col] + b1[col];
            float bia1 = b0[col + 1] + b1[col + 1];
            float w0v = vW[col];
            float w1v = vW[col + 1];
            #pragma unroll
            for (int mt = 0; mt < 2; mt++) {
                float* c = acc[mt][ng * 2 + j];
                rs[mt][0] += tanhf(c[0] + bia0) * w0v + tanhf(c[1] + bia1) * w1v;
                rs[mt][1] += tanhf(c[2] + bia0) * w0v + tanhf(c[3] + bia1) * w1v;
            }
        }

    #pragma unroll
    for (int mt = 0; mt < 2; mt++)
        #pragma unroll
        for (int h = 0; h < 2; h++) {
            rs[mt][h] += __shfl_xor_sync(0xffffffffu, rs[mt][h], 1);
            rs[mt][h] += __shfl_xor_sync(0xffffffffu, rs[mt][h], 2);
        }

    __syncthreads();
    if (tg == 0) {
        #pragma unroll
        for (int mt = 0; mt < 2; mt++)
            #pragma unroll
            for (int h = 0; h < 2; h++)
                sred[wm * 32 + mt * 16 + h * 8 + g][wn] = rs[mt][h];
    }
    __syncthreads();
    if (tid < 64) {
        g_spart[blockIdx.y * MM1 + mbase + tid] =
            sred[tid][0] + sred[tid][1] + sred[tid][2] + sred[tid][3];
    }
}

// ============================================================
// Generic split-K async GEMM (no bias): Cp[z] = A[:,k0:k0+kc] @ B[k0:k0+kc,:]
// grid (N/128, M/64, splits); NSTG=4; 3 blocks/SM. Requires kc/32 >= 3.
// ============================================================
__global__ __launch_bounds__(256, 3)
void gemm_async_part(const __half* __restrict__ Ah, int lda,
                     const __half* __restrict__ Bh, int N,
                     float* __restrict__ Cp, int kc) {
    extern __shared__ char smem[];
    const int tid = threadIdx.x;
    const int warp = tid >> 5, lane = tid & 31;
    const int wm = warp >> 2, wn = warp & 3;
    const int g = lane >> 2, tg = lane & 3;
    const int nbase = blockIdx.x * 128;
    const int mbase = blockIdx.y * 64;
    const int M = gridDim.y * 64;
    const int k0 = blockIdx.z * kc;
    float* C = Cp + (size_t)blockIdx.z * M * N;

    const uint32_t sbase = (uint32_t)__cvta_generic_to_shared(smem);
    const int sub = lane >> 3, li = lane & 7;
    const int ao = wm * 32 * AS2 + ((sub & 1) * 8 + li) * AS2 + (sub >> 1) * 16;
    const int bo = wn * 64 + ((sub & 1) * 8 + li) * BS2 + (sub >> 1) * 16;

    float acc[2][4][4];
    #pragma unroll
    for (int mt = 0; mt < 2; mt++)
        #pragma unroll
        for (int nt = 0; nt < 4; nt++)
            #pragma unroll
            for (int q = 0; q < 4; q++) acc[mt][nt][q] = 0.f;

    const int T = kc / 32;
    issue_t(sbase, 0 * STG, Ah, mbase, lda, Bh, nbase, N, k0, tid);
    issue_t(sbase, 1 * STG, Ah, mbase, lda, Bh, nbase, N, k0 + 32, tid);
    issue_t(sbase, 2 * STG, Ah, mbase, lda, Bh, nbase, N, k0 + 64, tid);

    for (int t = 0; t < T; t++) {
        cp_wait<2>();
        __syncthreads();
        uint32_t so = (uint32_t)(t & 3) * STG;
        mma_tile(acc, sbase + so + ao, sbase + so + STG_A + bo);
        if (t + 3 < T)
            issue_t(sbase, (uint32_t)((t + 3) & 3) * STG, Ah, mbase, lda, Bh, nbase, N,
                    k0 + (t + 3) * 32, tid);
        else
            cp_commit();
    }

    #pragma unroll
    for (int ng = 0; ng < 2; ng++)
        #pragma unroll
        for (int j = 0; j < 2; j++) {
            int col = nbase + wn * 32 + ng * 16 + j * 8 + 2 * tg;
            #pragma unroll
            for (int mt = 0; mt < 2; mt++) {
                int row = mbase + wm * 32 + mt * 16 + g;
                float* c = acc[mt][ng * 2 + j];
                *reinterpret_cast<float2*>(&C[(size_t)row * N + col]) =
                    make_float2(c[0], c[1]);
                *reinterpret_cast<float2*>(&C[(size_t)(row + 8) * N + col]) =
                    make_float2(c[2], c[3]);
            }
        }
}

// ============================================================
// Kernel 6: logits, NSTG=4, 3 blocks/SM; n0 = column-half base offset.
// grid (125, 2) per half.
// ============================================================
__global__ __launch_bounds__(256, 3)
void logits_async(const __half* __restrict__ Ah, const __half* __restrict__ Bh,
                  const float* __restrict__ bias, float* __restrict__ C, int n0) {
    extern __shared__ char smem[];
    const int tid = threadIdx.x;
    const int warp = tid >> 5, lane = tid & 31;
    const int wm = warp >> 2, wn = warp & 3;
    const int g = lane >> 2, tg = lane & 3;
    const int nbase = n0 + blockIdx.x * 128;
    const int mbase = blockIdx.y * 64;

    const uint32_t sbase = (uint32_t)__cvta_generic_to_shared(smem);
    const int sub = lane >> 3, li = lane & 7;
    const int ao = wm * 32 * AS2 + ((sub & 1) * 8 + li) * AS2 + (sub >> 1) * 16;
    const int bo = wn * 64 + ((sub & 1) * 8 + li) * BS2 + (sub >> 1) * 16;

    float acc[2][4][4];
    #pragma unroll
    for (int mt = 0; mt < 2; mt++)
        #pragma unroll
        for (int nt = 0; nt < 4; nt++)
            #pragma unroll
            for (int q = 0; q < 4; q++) acc[mt][nt][q] = 0.f;

    const int T = UU / 32;  // 16
    issue_t(sbase, 0 * STG, Ah, mbase, UU, Bh, nbase, VV, 0, tid);
    issue_t(sbase, 1 * STG, Ah, mbase, UU, Bh, nbase, VV, 32, tid);
    issue_t(sbase, 2 * STG, Ah, mbase, UU, Bh, nbase, VV, 64, tid);

    for (int t = 0; t < T; t++) {
        cp_wait<2>();
        __syncthreads();
        uint32_t so = (uint32_t)(t & 3) * STG;
        mma_tile(acc, sbase + so + ao, sbase + so + STG_A + bo);
        if (t + 3 < T)
            issue_t(sbase, (uint32_t)((t + 3) & 3) * STG, Ah, mbase, UU, Bh, nbase, VV,
                    (t + 3) * 32, tid);
        else
            cp_commit();
    }

    #pragma unroll
    for (int ng = 0; ng < 2; ng++)
        #pragma unroll
        for (int j = 0; j < 2; j++) {
            int col = nbase + wn * 32 + ng * 16 + j * 8 + 2 * tg;
            float bv0 = bias[col], bv1 = bias[col + 1];
            #pragma unroll
            for (int mt = 0; mt < 2; mt++) {
                int row = mbase + wm * 32 + mt * 16 + g;
                float* c = acc[mt][ng * 2 + j];
                *reinterpret_cast<float2*>(&C[(size_t)row * VV + col]) =
                    make_float2(c[0] + bv0, c[1] + bv1);
                *reinterpret_cast<float2*>(&C[(size_t)(row + 8) * VV + col]) =
                    make_float2(c[2] + bv0, c[3] + bv1);
            }
        }
}

// ============================================================
// Kernel 2: combine partials + softmax + context + fp16 concat (+ alpha)
// ============================================================
__global__ __launch_bounds__(128)
void ctx_kernel(const float* __restrict__ attn, const float* __restrict__ emb,
                const int* __restrict__ inputs, const float* __restrict__ vb,
                float* __restrict__ out_alpha) {
    __shared__ float sc[64];
    __shared__ float wred[2][2];
    const int b = blockIdx.x;
    const int tid = threadIdx.x;
    const int lane = tid & 31, wp = tid >> 5;

    if (tid < 64) {
        float v = vb[0] + g_spart[b * 64 + tid]
                + g_spart[MM1 + b * 64 + tid]
                + g_spart[2 * MM1 + b * 64 + tid]
                + g_spart[3 * MM1 + b * 64 + tid];
        float m = v;
        #pragma unroll
        for (int o = 16; o > 0; o >>= 1) m = fmaxf(m, __shfl_xor_sync(0xffffffffu, m, o));
        if (lane == 0) wred[wp][0] = m;
        __syncwarp();
        sc[tid] = v;
    }
    __syncthreads();
    float m = fmaxf(wred[0][0], wred[1][0]);
    if (tid < 64) {
        float e = __expf(sc[tid] - m);
        sc[tid] = e;
        float s = e;
        #pragma unroll
        for (int o = 16; o > 0; o >>= 1) s += __shfl_xor_sync(0xffffffffu, s, o);
        if (lane == 0) wred[wp][1] = s;
    }
    __syncthreads();
    float inv = 1.f / (wred[0][1] + wred[1][1]);
    if (tid < 64) {
        sc[tid] *= inv;
        if (out_alpha != nullptr) out_alpha[b * 64 + tid] = sc[tid];
    }
    __syncthreads();

    const int row = inputs[b];
    const float4* attn4 = reinterpret_cast<const float4*>(attn);
    const float4* emb4  = reinterpret_cast<const float4*>(emb);
    uint2* xch = reinterpret_cast<uint2*>(g_xc_h);

    float4 a = make_float4(0.f, 0.f, 0.f, 0.f);
    #pragma unroll 8
    for (int s = 0; s < 64; s++) {
        float4 t = attn4[(size_t)(b * 64 + s) * 128 + tid];
        float al = sc[s];
        a.x += t.x * al; a.y += t.y * al; a.z += t.z * al; a.w += t.w * al;
    }
    float4 e = emb4[(size_t)row * 128 + tid];
    xch[(size_t)b * 256 + 128 + tid] = make_uint2(packh2(a.x, a.y), packh2(a.z, a.w));
    xch[(size_t)b * 256 + tid] = make_uint2(packh2(e.x, e.y), packh2(e.z, e.w));
}

// ============================================================
// Kernel 4: GRU elementwise + gates split-K(4) reduce (h == 0 exact)
// ============================================================
__global__ __launch_bounds__(256)
void gru_kernel(const float* __restrict__ gru_b, float* __restrict__ out_state) {
    const int i4 = blockIdx.x * blockDim.x + threadIdx.x;
    if (i4 >= BB * UU / 4) return;
    const int b = i4 / (UU / 4);
    const int j4 = i4 % (UU / 4);
    const float4* gb = reinterpret_cast<const float4*>(gru_b);
    const float4* gp = reinterpret_cast<const float4*>(g_gpart);
    const int P = BB * 384;

    float4 xz, xr, xh;
    {
        float4 p0 = gp[(size_t)b * 384 + j4];
        float4 p1 = gp[P + (size_t)b * 384 + j4];
        float4 p2 = gp[2 * P + (size_t)b * 384 + j4];
        float4 p3 = gp[3 * P + (size_t)b * 384 + j4];
        xz = make_float4(p0.x + p1.x + p2.x + p3.x, p0.y + p1.y + p2.y + p3.y,
                         p0.z + p1.z + p2.z + p3.z, p0.w + p1.w + p2.w + p3.w);
        p0 = gp[(size_t)b * 384 + 128 + j4];
        p1 = gp[P + (size_t)b * 384 + 128 + j4];
        p2 = gp[2 * P + (size_t)b * 384 + 128 + j4];
        p3 = gp[3 * P + (size_t)b * 384 + 128 + j4];
        xr = make_float4(p0.x + p1.x + p2.x + p3.x, p0.y + p1.y + p2.y + p3.y,
                         p0.z + p1.z + p2.z + p3.z, p0.w + p1.w + p2.w + p3.w);
        p0 = gp[(size_t)b * 384 + 256 + j4];
        p1 = gp[P + (size_t)b * 384 + 256 + j4];
        p2 = gp[2 * P + (size_t)b * 384 + 256 + j4];
        p3 = gp[3 * P + (size_t)b * 384 + 256 + j4];
        xh = make_float4(p0.x + p1.x + p2.x + p3.x, p0.y + p1.y + p2.y + p3.y,
                         p0.z + p1.z + p2.z + p3.z, p0.w + p1.w + p2.w + p3.w);
    }
    float4 b0z = gb[j4],        b0r = gb[128 + j4], b0h = gb[256 + j4];
    float4 b1z = gb[384 + j4],  b1r = gb[512 + j4], b1h = gb[640 + j4];

    float4 st;
    {
        float z = 1.f / (1.f + __expf(-(xz.x + b0z.x + b1z.x)));
        float r = 1.f / (1.f + __expf(-(xr.x + b0r.x + b1r.x)));
        st.x = (1.f - z) * tanhf(xh.x + b0h.x + r * b1h.x);
        z = 1.f / (1.f + __expf(-(xz.y + b0z.y + b1z.y)));
        r = 1.f / (1.f + __expf(-(xr.y + b0r.y + b1r.y)));
        st.y = (1.f - z) * tanhf(xh.y + b0h.y + r * b1h.y);
        z = 1.f / (1.f + __expf(-(xz.z + b0z.z + b1z.z)));
        r = 1.f / (1.f + __expf(-(xr.z + b0r.z + b1r.z)));
        st.z = (1.f - z) * tanhf(xh.z + b0h.z + r * b1h.z);
        z = 1.f / (1.f + __expf(-(xz.w + b0z.w + b1z.w)));
        r = 1.f / (1.f + __expf(-(xr.w + b0r.w + b1r.w)));
        st.w = (1.f - z) * tanhf(xh.w + b0h.w + r * b1h.w);
    }

    reinterpret_cast<uint2*>(g_state_h)[i4] =
        make_uint2(packh2(st.x, st.y), packh2(st.z, st.w));
    if (out_state != nullptr) reinterpret_cast<float4*>(out_state)[i4] = st;
}

// ============================================================
// Kernel 5b: dense split-K(4) reduce + bias + relu -> g_y_h (fp16)
// ============================================================
__global__ __launch_bounds__(256)
void dense_reduce(const float* __restrict__ db) {
    const int i4 = blockIdx.x * blockDim.x + threadIdx.x;
    if (i4 >= BB * UU / 4) return;
    const int j4 = i4 % (UU / 4);
    const float4* yp = reinterpret_cast<const float4*>(g_ypart);
    const float4* db4 = reinterpret_cast<const float4*>(db);
    const int P = BB * UU / 4;

    float4 p0 = yp[i4], p1 = yp[P + i4], p2 = yp[2 * P + i4], p3 = yp[3 * P + i4];
    float4 bv = db4[j4];
    float4 v = make_float4(fmaxf(p0.x + p1.x + p2.x + p3.x + bv.x, 0.f),
                           fmaxf(p0.y + p1.y + p2.y + p3.y + bv.y, 0.f),
                           fmaxf(p0.z + p1.z + p2.z + p3.z + bv.z, 0.f),
                           fmaxf(p0.w + p1.w + p2.w + p3.w + bv.w, 0.f));
    reinterpret_cast<uint2*>(g_y_h)[i4] = make_uint2(packh2(v.x, v.y), packh2(v.z, v.w));
}

// ============================================================
// Launch — side stream: oW cols half1 (ev2a) -> gru_k+dW (ev1) ->
// oW cols half2 (ev2b). Logits runs in two N-halves joining ev2a/ev2b.
// ============================================================
extern "C" void kernel_launch(void* const* d_in, const int* in_sizes, int n_in,
                              void* d_out, int out_size) {
    const int*   inputs = (const int*)  d_in[0];
    const float* attn   = (const float*)d_in[1];
    const float* W0     = (const float*)d_in[2];
    const float* b0     = (const float*)d_in[3];
    // d_in[4] = W1   (dead: hidden0 == 0)
    const float* b1     = (const float*)d_in[5];
    const float* vW     = (const float*)d_in[6];
    const float* vb     = (const float*)d_in[7];
    const float* emb    = (const float*)d_in[8];
    const float* gru_k  = (const float*)d_in[9];
    // d_in[10] = gru_rk (dead: h == 0)
    const float* gru_b  = (const float*)d_in[11];
    const float* dW     = (const float*)d_in[12];
    const float* db     = (const float*)d_in[13];
    const float* oW     = (const float*)d_in[14];
    const float* ob     = (const float*)d_in[15];

    float* out = (float*)d_out;
    float* out_logits = out;
    float* out_state = nullptr;
    float* out_alpha = nullptr;
    if (out_size >= BB * VV + BB * UU + BB * SS) {
        out_state = out + (size_t)BB * VV;
        out_alpha = out_state + (size_t)BB * UU;
    }

    float *p_gpart, *p_ypart;
    __half *p_attn_h, *p_W0_h, *p_gruk_h, *p_dW_h, *p_oW_h, *p_xc_h, *p_state_h, *p_y_h;
    cudaGetSymbolAddress((void**)&p_gpart, g_gpart);
    cudaGetSymbolAddress((void**)&p_ypart, g_ypart);
    cudaGetSymbolAddress((void**)&p_attn_h, g_attn_h);
    cudaGetSymbolAddress((void**)&p_W0_h, g_W0_h);
    cudaGetSymbolAddress((void**)&p_gruk_h, g_gruk_h);
    cudaGetSymbolAddress((void**)&p_dW_h, g_dW_h);
    cudaGetSymbolAddress((void**)&p_oW_h, g_oW_h);
    cudaGetSymbolAddress((void**)&p_xc_h, g_xc_h);
    cudaGetSymbolAddress((void**)&p_state_h, g_state_h);
    cudaGetSymbolAddress((void**)&p_y_h, g_y_h);

    const int smemScore = 4 * STG + 64 * 4 * 4;  // 56320
    const int smemPart  = 4 * STG;               // 55296
    const int smemLog   = 4 * STG;               // 55296
    const int HALF_V = VV / 2;                   // 16000
    const int HALF_N8 = HALF_V / 8;              // 2000 col-chunks per row

    static cudaStream_t s2 = nullptr;
    static cudaEvent_t evFork = nullptr, ev1 = nullptr, ev2a = nullptr, ev2b = nullptr;
    static bool init_done = false;
    if (!init_done) {
        cudaFuncSetAttribute(score_async, cudaFuncAttributeMaxDynamicSharedMemorySize, smemScore);
        cudaFuncSetAttribute(gemm_async_part, cudaFuncAttributeMaxDynamicSharedMemorySize, smemPart);
        cudaFuncSetAttribute(logits_async, cudaFuncAttributeMaxDynamicSharedMemorySize, smemLog);
        cudaStreamCreateWithFlags(&s2, cudaStreamNonBlocking);
        cudaEventCreateWithFlags(&evFork, cudaEventDisableTiming);
        cudaEventCreateWithFlags(&ev1, cudaEventDisableTiming);
        cudaEventCreateWithFlags(&ev2a, cudaEventDisableTiming);
        cudaEventCreateWithFlags(&ev2b, cudaEventDisableTiming);
        init_done = true;
    }

    // 0a) fork side stream: oW cols [0,16000) -> ev2a; gru_k+dW -> ev1;
    //     oW cols [16000,32000) -> ev2b. Full grids (bandwidth machines).
    cudaEventRecord(evFork, 0);
    cudaStreamWaitEvent(s2, evFork, 0);
    f2h_cols<<<(UU * HALF_N8 + 255) / 256, 256, 0, s2>>>(oW, p_oW_h, VV, 0, HALF_N8);
    cudaEventRecord(ev2a, s2);
    f2h_dual<<<(2 * UU * 3 * UU / 8 + UU * UU / 8 + 255) / 256, 256, 0, s2>>>(
        gru_k, p_gruk_h, 2 * UU * 3 * UU / 8, dW, p_dW_h, UU * UU / 8);
    cudaEventRecord(ev1, s2);
    f2h_cols<<<(UU * HALF_N8 + 255) / 256, 256, 0, s2>>>(oW, p_oW_h, VV, HALF_V, HALF_N8);
    cudaEventRecord(ev2b, s2);

    // 0b) attn + W0 conversions (critical path, full grid)
    f2h_dual<<<(MM1 * UU / 8 + UU * UU / 8 + 255) / 256, 256>>>(
        attn, p_attn_h, MM1 * UU / 8, W0, p_W0_h, UU * UU / 8);

    // 1) attention score partials: cp.async pipeline, grid (128, 4)
    score_async<<<dim3(MM1 / 64, 4), 256, smemScore>>>(p_attn_h, p_W0_h, b0, b1, vW);
    // 2) combine partials + softmax + context + fp16 concat (+ alpha output)
    ctx_kernel<<<BB, 128>>>(attn, emb, inputs, vb, out_alpha);

    // 3) gates split-K(4): xc_h[128,1024] @ gru_k_h[1024,1536], grid (12,2,4)
    cudaStreamWaitEvent(0, ev1, 0);
    gemm_async_part<<<dim3(3 * UU / 128, BB / 64, 4), 256, smemPart>>>(
        p_xc_h, 2 * UU, p_gruk_h, 3 * UU, p_gpart, 2 * UU / 4);
    // 4) GRU nonlinearity + gates reduce (+ state output)
    gru_kernel<<<BB * UU / 4 / 256, 256>>>(gru_b, out_state);
    // 5) dense split-K(4): state_h[128,512] @ dW_h[512,512], grid (4,2,4)
    gemm_async_part<<<dim3(UU / 128, BB / 64, 4), 256, smemPart>>>(
        p_state_h, UU, p_dW_h, UU, p_ypart, UU / 4);
    // 5b) dense reduce + bias + relu -> fp16 y
    dense_reduce<<<BB * UU / 4 / 256, 256>>>(db);

    // 6) logits in two N-halves: half 1 joins ev2a, half 2 joins ev2b
    cudaStreamWaitEvent(0, ev2a, 0);
    logits_async<<<dim3(HALF_V / 128, BB / 64), 256, smemLog>>>(p_y_h, p_oW_h, ob,
                                                                out_logits, 0);
    cudaStreamWaitEvent(0, ev2b, 0);
    logits_async<<<dim3(HALF_V / 128, BB / 64), 256, smemLog>>>(p_y_h, p_oW_h, ob,
                                                                out_logits, HALF_V);
}

// round 17
// speedup vs baseline: 1.0097x; 1.0097x over previous
#include <cuda_runtime.h>
#include <cuda_fp16.h>
#include <math.h>
#include <stdint.h>

// Shapes
#define BB 128      // batch
#define SS 64       // seq
#define UU 512      // units
#define VV 32000    // vocab
#define MM1 (BB*SS) // 8192 rows for the attention GEMM

// async pipeline tile geometry: BM=64, BN=128, BK=32; 256 threads
#define AS2 80                      // A row stride bytes (64B fp16 data + 16 pad)
#define BS2 272                     // B row stride bytes (256B fp16 data + 16 pad)
#define STG_A (64 * AS2)            // 5120
#define STG_B (32 * BS2)            // 8704
#define STG   (STG_A + STG_B)       // 13824

// -------------------- scratch (no allocations allowed) --------------------
__device__ float  g_spart[4 * MM1];           // score partial sums (4 N-slices)
__device__ __half g_xc_h[BB * 2 * UU];        // [x | context] fp16
__device__ float  g_gpart[4 * BB * 3 * UU];   // GRU gates split-K partials
__device__ float  g_ypart[4 * BB * UU];       // dense split-K partials
__device__ __half g_state_h[BB * UU];         // GRU state fp16 (dense A operand)
__device__ __half g_y_h[BB * UU];             // dense output fp16 (logits A operand)
__device__ __half g_attn_h[MM1 * UU];         // fp16 attn
__device__ __half g_W0_h[UU * UU];            // fp16 W0  [k][n]
__device__ __half g_gruk_h[2 * UU * 3 * UU];  // fp16 gru_k [k][n]
__device__ __half g_dW_h[UU * UU];            // fp16 dW [k][n]
__device__ __half g_oW_h[(size_t)UU * VV];    // fp16 oW [k][v]

// -------------------- helpers --------------------
__device__ __forceinline__ uint32_t packh2(float lo, float hi) {
    half2 h = __floats2half2_rn(lo, hi);
    return *reinterpret_cast<uint32_t*>(&h);
}

__device__ __forceinline__ void mma_f16(float c[4],
                                        uint32_t a0, uint32_t a1, uint32_t a2, uint32_t a3,
                                        uint32_t b0, uint32_t b1) {
    asm volatile(
        "mma.sync.aligned.m16n8k16.row.col.f32.f16.f16.f32 "
        "{%0,%1,%2,%3}, {%4,%5,%6,%7}, {%8,%9}, {%0,%1,%2,%3};"
        : "+f"(c[0]), "+f"(c[1]), "+f"(c[2]), "+f"(c[3])
        : "r"(a0), "r"(a1), "r"(a2), "r"(a3), "r"(b0), "r"(b1));
}

__device__ __forceinline__ void ldsm4(uint32_t& r0, uint32_t& r1, uint32_t& r2, uint32_t& r3,
                                      uint32_t addr) {
    asm volatile("ldmatrix.sync.aligned.m8n8.x4.shared.b16 {%0,%1,%2,%3}, [%4];"
                 : "=r"(r0), "=r"(r1), "=r"(r2), "=r"(r3) : "r"(addr));
}
__device__ __forceinline__ void ldsm4t(uint32_t& r0, uint32_t& r1, uint32_t& r2, uint32_t& r3,
                                       uint32_t addr) {
    asm volatile("ldmatrix.sync.aligned.m8n8.x4.trans.shared.b16 {%0,%1,%2,%3}, [%4];"
                 : "=r"(r0), "=r"(r1), "=r"(r2), "=r"(r3) : "r"(addr));
}

__device__ __forceinline__ void cp_async16(uint32_t dst, const void* src) {
    asm volatile("cp.async.cg.shared.global [%0], [%1], 16;" :: "r"(dst), "l"(src));
}
__device__ __forceinline__ void cp_commit() {
    asm volatile("cp.async.commit_group;" ::: "memory");
}
template<int N> __device__ __forceinline__ void cp_wait() {
    asm volatile("cp.async.wait_group %0;" :: "n"(N) : "memory");
}

// issue one 64x32 A tile + 32x128 B tile into a pipeline slot (256 threads)
__device__ __forceinline__ void issue_t(uint32_t sbase, uint32_t slotOff,
                                        const __half* __restrict__ Ah, int mbase, int lda,
                                        const __half* __restrict__ Bh, int nbase, int ldb,
                                        int kb, int tid) {
    uint32_t sA = sbase + slotOff;
    uint32_t sB = sA + STG_A;
    int arow = tid >> 2, apart = tid & 3;
    cp_async16(sA + arow * AS2 + apart * 16,
               Ah + (size_t)(mbase + arow) * lda + kb + apart * 8);
    #pragma unroll
    for (int it = 0; it < 2; it++) {
        int i = tid + it * 256;
        int row = i >> 4, part = i & 15;
        cp_async16(sB + row * BS2 + part * 16,
                   Bh + (size_t)(kb + row) * ldb + nbase + part * 8);
    }
    cp_commit();
}

// fragment compute over one staged tile; warp (wm,wn) handles 32x32 region
__device__ __forceinline__ void mma_tile(float (&acc)[2][4][4], uint32_t aA, uint32_t aB) {
    #pragma unroll
    for (int ks = 0; ks < 2; ks++) {
        uint32_t a[2][4], b[2][4];
        #pragma unroll
        for (int mt = 0; mt < 2; mt++)
            ldsm4(a[mt][0], a[mt][1], a[mt][2], a[mt][3],
                  aA + mt * 16 * AS2 + ks * 32);
        #pragma unroll
        for (int ng = 0; ng < 2; ng++)
            ldsm4t(b[ng][0], b[ng][1], b[ng][2], b[ng][3],
                   aB + ng * 32 + ks * 16 * BS2);
        #pragma unroll
        for (int mt = 0; mt < 2; mt++)
            #pragma unroll
            for (int nt = 0; nt < 4; nt++) {
                int ng = nt >> 1, lo = (nt & 1) * 2;
                mma_f16(acc[mt][nt], a[mt][0], a[mt][1], a[mt][2], a[mt][3],
                        b[ng][lo], b[ng][lo + 1]);
            }
    }
}

// ============================================================
// fp32 -> fp16 conversions (full grid; they are bandwidth machines)
// ============================================================
__global__ __launch_bounds__(256)
void f2h_dual(const float* __restrict__ sa, __half* __restrict__ da, int n8a,
              const float* __restrict__ sb, __half* __restrict__ db, int n8b) {
    int i = blockIdx.x * blockDim.x + threadIdx.x;
    const float4* s4;
    uint4* d4;
    int j;
    if (i < n8a) { s4 = reinterpret_cast<const float4*>(sa); d4 = reinterpret_cast<uint4*>(da); j = i; }
    else { j = i - n8a; if (j >= n8b) return;
           s4 = reinterpret_cast<const float4*>(sb); d4 = reinterpret_cast<uint4*>(db); }
    float4 a = s4[2 * j], b = s4[2 * j + 1];
    uint4 o;
    o.x = packh2(a.x, a.y); o.y = packh2(a.z, a.w);
    o.z = packh2(b.x, b.y); o.w = packh2(b.z, b.w);
    d4[j] = o;
}
// column-range conversion: convert cols [c0, c0 + ncols8*8) of a [UU][ld] matrix
__global__ __launch_bounds__(256)
void f2h_cols(const float* __restrict__ src, __half* __restrict__ dst,
              int ld, int c0, int ncols8) {
    int i = blockIdx.x * blockDim.x + threadIdx.x;
    int total = UU * ncols8;
    if (i >= total) return;
    int k = i / ncols8, c8 = i % ncols8;
    const float4* s4 = reinterpret_cast<const float4*>(src + (size_t)k * ld + c0 + c8 * 8);
    float4 a = s4[0], b = s4[1];
    uint4 o;
    o.x = packh2(a.x, a.y); o.y = packh2(a.z, a.w);
    o.z = packh2(b.x, b.y); o.w = packh2(b.z, b.w);
    *reinterpret_cast<uint4*>(dst + (size_t)k * ld + c0 + c8 * 8) = o;
}

// ============================================================
// Kernel 1: score partials. NSTG=4, forced 3 blocks/SM. grid (128, 4).
// ============================================================
__global__ __launch_bounds__(256, 3)
void score_async(const __half* __restrict__ Ah, const __half* __restrict__ Bh,
                 const float* __restrict__ b0, const float* __restrict__ b1,
                 const float* __restrict__ vW) {
    extern __shared__ char smem[];
    float (*sred)[4] = reinterpret_cast<float (*)[4]>(smem + 4 * STG);

    const int tid = threadIdx.x;
    const int warp = tid >> 5, lane = tid & 31;
    const int wm = warp >> 2, wn = warp & 3;
    const int g = lane >> 2, tg = lane & 3;
    const int mbase = blockIdx.x * 64;
    const int nbase = blockIdx.y * 128;

    const uint32_t sbase = (uint32_t)__cvta_generic_to_shared(smem);
    const int sub = lane >> 3, li = lane & 7;
    const int ao = wm * 32 * AS2 + ((sub & 1) * 8 + li) * AS2 + (sub >> 1) * 16;
    const int bo = wn * 64 + ((sub & 1) * 8 + li) * BS2 + (sub >> 1) * 16;

    float acc[2][4][4];
    #pragma unroll
    for (int mt = 0; mt < 2; mt++)
        #pragma unroll
        for (int nt = 0; nt < 4; nt++)
            #pragma unroll
            for (int q = 0; q < 4; q++) acc[mt][nt][q] = 0.f;

    const int T = UU / 32;  // 16
    issue_t(sbase, 0 * STG, Ah, mbase, UU, Bh, nbase, UU, 0, tid);
    issue_t(sbase, 1 * STG, Ah, mbase, UU, Bh, nbase, UU, 32, tid);
    issue_t(sbase, 2 * STG, Ah, mbase, UU, Bh, nbase, UU, 64, tid);

    for (int t = 0; t < T; t++) {
        cp_wait<2>();
        __syncthreads();
        uint32_t so = (uint32_t)(t & 3) * STG;
        mma_tile(acc, sbase + so + ao, sbase + so + STG_A + bo);
        if (t + 3 < T)
            issue_t(sbase, (uint32_t)((t + 3) & 3) * STG, Ah, mbase, UU, Bh, nbase, UU,
                    (t + 3) * 32, tid);
        else
            cp_commit();
    }

    // fused epilogue: tanh(+bias) * vW -> per-row partial sums
    float rs[2][2] = {{0.f, 0.f}, {0.f, 0.f}};
    #pragma unroll
    for (int ng = 0; ng < 2; ng++)
        #pragma unroll
        for (int j = 0; j < 2; j++) {
            int col = nbase + wn * 32 + ng * 16 + j * 8 + 2 * tg;
            float bia0 = b0[col] + b1[col];
            float bia1 = b0[col + 1] + b1[col + 1];
            float w0v = vW[col];
            float w1v = vW[col + 1];
            #pragma unroll
            for (int mt = 0; mt < 2; mt++) {
                float* c = acc[mt][ng * 2 + j];
                rs[mt][0] += tanhf(c[0] + bia0) * w0v + tanhf(c[1] + bia1) * w1v;
                rs[mt][1] += tanhf(c[2] + bia0) * w0v + tanhf(c[3] + bia1) * w1v;
            }
        }

    #pragma unroll
    for (int mt = 0; mt < 2; mt++)
        #pragma unroll
        for (int h = 0; h < 2; h++) {
            rs[mt][h] += __shfl_xor_sync(0xffffffffu, rs[mt][h], 1);
            rs[mt][h] += __shfl_xor_sync(0xffffffffu, rs[mt][h], 2);
        }

    __syncthreads();
    if (tg == 0) {
        #pragma unroll
        for (int mt = 0; mt < 2; mt++)
            #pragma unroll
            for (int h = 0; h < 2; h++)
                sred[wm * 32 + mt * 16 + h * 8 + g][wn] = rs[mt][h];
    }
    __syncthreads();
    if (tid < 64) {
        g_spart[blockIdx.y * MM1 + mbase + tid] =
            sred[tid][0] + sred[tid][1] + sred[tid][2] + sred[tid][3];
    }
}

// ============================================================
// Generic split-K async GEMM (no bias): Cp[z] = A[:,k0:k0+kc] @ B[k0:k0+kc,:]
// grid (N/128, M/64, splits); NSTG=4; 3 blocks/SM. Requires kc/32 >= 3.
// ============================================================
__global__ __launch_bounds__(256, 3)
void gemm_async_part(const __half* __restrict__ Ah, int lda,
                     const __half* __restrict__ Bh, int N,
                     float* __restrict__ Cp, int kc) {
    extern __shared__ char smem[];
    const int tid = threadIdx.x;
    const int warp = tid >> 5, lane = tid & 31;
    const int wm = warp >> 2, wn = warp & 3;
    const int g = lane >> 2, tg = lane & 3;
    const int nbase = blockIdx.x * 128;
    const int mbase = blockIdx.y * 64;
    const int M = gridDim.y * 64;
    const int k0 = blockIdx.z * kc;
    float* C = Cp + (size_t)blockIdx.z * M * N;

    const uint32_t sbase = (uint32_t)__cvta_generic_to_shared(smem);
    const int sub = lane >> 3, li = lane & 7;
    const int ao = wm * 32 * AS2 + ((sub & 1) * 8 + li) * AS2 + (sub >> 1) * 16;
    const int bo = wn * 64 + ((sub & 1) * 8 + li) * BS2 + (sub >> 1) * 16;

    float acc[2][4][4];
    #pragma unroll
    for (int mt = 0; mt < 2; mt++)
        #pragma unroll
        for (int nt = 0; nt < 4; nt++)
            #pragma unroll
            for (int q = 0; q < 4; q++) acc[mt][nt][q] = 0.f;

    const int T = kc / 32;
    issue_t(sbase, 0 * STG, Ah, mbase, lda, Bh, nbase, N, k0, tid);
    issue_t(sbase, 1 * STG, Ah, mbase, lda, Bh, nbase, N, k0 + 32, tid);
    issue_t(sbase, 2 * STG, Ah, mbase, lda, Bh, nbase, N, k0 + 64, tid);

    for (int t = 0; t < T; t++) {
        cp_wait<2>();
        __syncthreads();
        uint32_t so = (uint32_t)(t & 3) * STG;
        mma_tile(acc, sbase + so + ao, sbase + so + STG_A + bo);
        if (t + 3 < T)
            issue_t(sbase, (uint32_t)((t + 3) & 3) * STG, Ah, mbase, lda, Bh, nbase, N,
                    k0 + (t + 3) * 32, tid);
        else
            cp_commit();
    }

    #pragma unroll
    for (int ng = 0; ng < 2; ng++)
        #pragma unroll
        for (int j = 0; j < 2; j++) {
            int col = nbase + wn * 32 + ng * 16 + j * 8 + 2 * tg;
            #pragma unroll
            for (int mt = 0; mt < 2; mt++) {
                int row = mbase + wm * 32 + mt * 16 + g;
                float* c = acc[mt][ng * 2 + j];
                *reinterpret_cast<float2*>(&C[(size_t)row * N + col]) =
                    make_float2(c[0], c[1]);
                *reinterpret_cast<float2*>(&C[(size_t)(row + 8) * N + col]) =
                    make_float2(c[2], c[3]);
            }
        }
}

// ============================================================
// Kernel 6: logits, NSTG=4, 3 blocks/SM; n0 = column-half base offset.
// grid (125, 2) per half.
// ============================================================
__global__ __launch_bounds__(256, 3)
void logits_async(const __half* __restrict__ Ah, const __half* __restrict__ Bh,
                  const float* __restrict__ bias, float* __restrict__ C, int n0) {
    extern __shared__ char smem[];
    const int tid = threadIdx.x;
    const int warp = tid >> 5, lane = tid & 31;
    const int wm = warp >> 2, wn = warp & 3;
    const int g = lane >> 2, tg = lane & 3;
    const int nbase = n0 + blockIdx.x * 128;
    const int mbase = blockIdx.y * 64;

    const uint32_t sbase = (uint32_t)__cvta_generic_to_shared(smem);
    const int sub = lane >> 3, li = lane & 7;
    const int ao = wm * 32 * AS2 + ((sub & 1) * 8 + li) * AS2 + (sub >> 1) * 16;
    const int bo = wn * 64 + ((sub & 1) * 8 + li) * BS2 + (sub >> 1) * 16;

    float acc[2][4][4];
    #pragma unroll
    for (int mt = 0; mt < 2; mt++)
        #pragma unroll
        for (int nt = 0; nt < 4; nt++)
            #pragma unroll
            for (int q = 0; q < 4; q++) acc[mt][nt][q] = 0.f;

    const int T = UU / 32;  // 16
    issue_t(sbase, 0 * STG, Ah, mbase, UU, Bh, nbase, VV, 0, tid);
    issue_t(sbase, 1 * STG, Ah, mbase, UU, Bh, nbase, VV, 32, tid);
    issue_t(sbase, 2 * STG, Ah, mbase, UU, Bh, nbase, VV, 64, tid);

    for (int t = 0; t < T; t++) {
        cp_wait<2>();
        __syncthreads();
        uint32_t so = (uint32_t)(t & 3) * STG;
        mma_tile(acc, sbase + so + ao, sbase + so + STG_A + bo);
        if (t + 3 < T)
            issue_t(sbase, (uint32_t)((t + 3) & 3) * STG, Ah, mbase, UU, Bh, nbase, VV,
                    (t + 3) * 32, tid);
        else
            cp_commit();
    }

    #pragma unroll
    for (int ng = 0; ng < 2; ng++)
        #pragma unroll
        for (int j = 0; j < 2; j++) {
            int col = nbase + wn * 32 + ng * 16 + j * 8 + 2 * tg;
            float bv0 = bias[col], bv1 = bias[col + 1];
            #pragma unroll
            for (int mt = 0; mt < 2; mt++) {
                int row = mbase + wm * 32 + mt * 16 + g;
                float* c = acc[mt][ng * 2 + j];
                *reinterpret_cast<float2*>(&C[(size_t)row * VV + col]) =
                    make_float2(c[0] + bv0, c[1] + bv1);
                *reinterpret_cast<float2*>(&C[(size_t)(row + 8) * VV + col]) =
                    make_float2(c[2] + bv0, c[3] + bv1);
            }
        }
}

// ============================================================
// Kernel 2: combine partials + softmax + context + fp16 concat (+ alpha)
// ============================================================
__global__ __launch_bounds__(128)
void ctx_kernel(const float* __restrict__ attn, const float* __restrict__ emb,
                const int* __restrict__ inputs, const float* __restrict__ vb,
                float* __restrict__ out_alpha) {
    __shared__ float sc[64];
    __shared__ float wred[2][2];
    const int b = blockIdx.x;
    const int tid = threadIdx.x;
    const int lane = tid & 31, wp = tid >> 5;

    if (tid < 64) {
        float v = vb[0] + g_spart[b * 64 + tid]
                + g_spart[MM1 + b * 64 + tid]
                + g_spart[2 * MM1 + b * 64 + tid]
                + g_spart[3 * MM1 + b * 64 + tid];
        float m = v;
        #pragma unroll
        for (int o = 16; o > 0; o >>= 1) m = fmaxf(m, __shfl_xor_sync(0xffffffffu, m, o));
        if (lane == 0) wred[wp][0] = m;
        __syncwarp();
        sc[tid] = v;
    }
    __syncthreads();
    float m = fmaxf(wred[0][0], wred[1][0]);
    if (tid < 64) {
        float e = __expf(sc[tid] - m);
        sc[tid] = e;
        float s = e;
        #pragma unroll
        for (int o = 16; o > 0; o >>= 1) s += __shfl_xor_sync(0xffffffffu, s, o);
        if (lane == 0) wred[wp][1] = s;
    }
    __syncthreads();
    float inv = 1.f / (wred[0][1] + wred[1][1]);
    if (tid < 64) {
        sc[tid] *= inv;
        if (out_alpha != nullptr) out_alpha[b * 64 + tid] = sc[tid];
    }
    __syncthreads();

    const int row = inputs[b];
    const float4* attn4 = reinterpret_cast<const float4*>(attn);
    const float4* emb4  = reinterpret_cast<const float4*>(emb);
    uint2* xch = reinterpret_cast<uint2*>(g_xc_h);

    float4 a = make_float4(0.f, 0.f, 0.f, 0.f);
    #pragma unroll 8
    for (int s = 0; s < 64; s++) {
        float4 t = attn4[(size_t)(b * 64 + s) * 128 + tid];
        float al = sc[s];
        a.x += t.x * al; a.y += t.y * al; a.z += t.z * al; a.w += t.w * al;
    }
    float4 e = emb4[(size_t)row * 128 + tid];
    xch[(size_t)b * 256 + 128 + tid] = make_uint2(packh2(a.x, a.y), packh2(a.z, a.w));
    xch[(size_t)b * 256 + tid] = make_uint2(packh2(e.x, e.y), packh2(e.z, e.w));
}

// ============================================================
// Kernel 4: GRU elementwise + gates split-K(4) reduce (h == 0 exact)
// ============================================================
__global__ __launch_bounds__(256)
void gru_kernel(const float* __restrict__ gru_b, float* __restrict__ out_state) {
    const int i4 = blockIdx.x * blockDim.x + threadIdx.x;
    if (i4 >= BB * UU / 4) return;
    const int b = i4 / (UU / 4);
    const int j4 = i4 % (UU / 4);
    const float4* gb = reinterpret_cast<const float4*>(gru_b);
    const float4* gp = reinterpret_cast<const float4*>(g_gpart);
    const int P = BB * 384;

    float4 xz, xr, xh;
    {
        float4 p0 = gp[(size_t)b * 384 + j4];
        float4 p1 = gp[P + (size_t)b * 384 + j4];
        float4 p2 = gp[2 * P + (size_t)b * 384 + j4];
        float4 p3 = gp[3 * P + (size_t)b * 384 + j4];
        xz = make_float4(p0.x + p1.x + p2.x + p3.x, p0.y + p1.y + p2.y + p3.y,
                         p0.z + p1.z + p2.z + p3.z, p0.w + p1.w + p2.w + p3.w);
        p0 = gp[(size_t)b * 384 + 128 + j4];
        p1 = gp[P + (size_t)b * 384 + 128 + j4];
        p2 = gp[2 * P + (size_t)b * 384 + 128 + j4];
        p3 = gp[3 * P + (size_t)b * 384 + 128 + j4];
        xr = make_float4(p0.x + p1.x + p2.x + p3.x, p0.y + p1.y + p2.y + p3.y,
                         p0.z + p1.z + p2.z + p3.z, p0.w + p1.w + p2.w + p3.w);
        p0 = gp[(size_t)b * 384 + 256 + j4];
        p1 = gp[P + (size_t)b * 384 + 256 + j4];
        p2 = gp[2 * P + (size_t)b * 384 + 256 + j4];
        p3 = gp[3 * P + (size_t)b * 384 + 256 + j4];
        xh = make_float4(p0.x + p1.x + p2.x + p3.x, p0.y + p1.y + p2.y + p3.y,
                         p0.z + p1.z + p2.z + p3.z, p0.w + p1.w + p2.w + p3.w);
    }
    float4 b0z = gb[j4],        b0r = gb[128 + j4], b0h = gb[256 + j4];
    float4 b1z = gb[384 + j4],  b1r = gb[512 + j4], b1h = gb[640 + j4];

    float4 st;
    {
        float z = 1.f / (1.f + __expf(-(xz.x + b0z.x + b1z.x)));
        float r = 1.f / (1.f + __expf(-(xr.x + b0r.x + b1r.x)));
        st.x = (1.f - z) * tanhf(xh.x + b0h.x + r * b1h.x);
        z = 1.f / (1.f + __expf(-(xz.y + b0z.y + b1z.y)));
        r = 1.f / (1.f + __expf(-(xr.y + b0r.y + b1r.y)));
        st.y = (1.f - z) * tanhf(xh.y + b0h.y + r * b1h.y);
        z = 1.f / (1.f + __expf(-(xz.z + b0z.z + b1z.z)));
        r = 1.f / (1.f + __expf(-(xr.z + b0r.z + b1r.z)));
        st.z = (1.f - z) * tanhf(xh.z + b0h.z + r * b1h.z);
        z = 1.f / (1.f + __expf(-(xz.w + b0z.w + b1z.w)));
        r = 1.f / (1.f + __expf(-(xr.w + b0r.w + b1r.w)));
        st.w = (1.f - z) * tanhf(xh.w + b0h.w + r * b1h.w);
    }

    reinterpret_cast<uint2*>(g_state_h)[i4] =
        make_uint2(packh2(st.x, st.y), packh2(st.z, st.w));
    if (out_state != nullptr) reinterpret_cast<float4*>(out_state)[i4] = st;
}

// ============================================================
// Kernel 5b: dense split-K(4) reduce + bias + relu -> g_y_h (fp16)
// ============================================================
__global__ __launch_bounds__(256)
void dense_reduce(const float* __restrict__ db) {
    const int i4 = blockIdx.x * blockDim.x + threadIdx.x;
    if (i4 >= BB * UU / 4) return;
    const int j4 = i4 % (UU / 4);
    const float4* yp = reinterpret_cast<const float4*>(g_ypart);
    const float4* db4 = reinterpret_cast<const float4*>(db);
    const int P = BB * UU / 4;

    float4 p0 = yp[i4], p1 = yp[P + i4], p2 = yp[2 * P + i4], p3 = yp[3 * P + i4];
    float4 bv = db4[j4];
    float4 v = make_float4(fmaxf(p0.x + p1.x + p2.x + p3.x + bv.x, 0.f),
                           fmaxf(p0.y + p1.y + p2.y + p3.y + bv.y, 0.f),
                           fmaxf(p0.z + p1.z + p2.z + p3.z + bv.z, 0.f),
                           fmaxf(p0.w + p1.w + p2.w + p3.w + bv.w, 0.f));
    reinterpret_cast<uint2*>(g_y_h)[i4] = make_uint2(packh2(v.x, v.y), packh2(v.z, v.w));
}

// ============================================================
// Launch — side stream: oW cols half1 (ev2a) -> gru_k+dW (ev1) ->
// oW cols half2 (ev2b). Logits runs in two N-halves joining ev2a/ev2b.
// ============================================================
extern "C" void kernel_launch(void* const* d_in, const int* in_sizes, int n_in,
                              void* d_out, int out_size) {
    const int*   inputs = (const int*)  d_in[0];
    const float* attn   = (const float*)d_in[1];
    const float* W0     = (const float*)d_in[2];
    const float* b0     = (const float*)d_in[3];
    // d_in[4] = W1   (dead: hidden0 == 0)
    const float* b1     = (const float*)d_in[5];
    const float* vW     = (const float*)d_in[6];
    const float* vb     = (const float*)d_in[7];
    const float* emb    = (const float*)d_in[8];
    const float* gru_k  = (const float*)d_in[9];
    // d_in[10] = gru_rk (dead: h == 0)
    const float* gru_b  = (const float*)d_in[11];
    const float* dW     = (const float*)d_in[12];
    const float* db     = (const float*)d_in[13];
    const float* oW     = (const float*)d_in[14];
    const float* ob     = (const float*)d_in[15];

    float* out = (float*)d_out;
    float* out_logits = out;
    float* out_state = nullptr;
    float* out_alpha = nullptr;
    if (out_size >= BB * VV + BB * UU + BB * SS) {
        out_state = out + (size_t)BB * VV;
        out_alpha = out_state + (size_t)BB * UU;
    }

    float *p_gpart, *p_ypart;
    __half *p_attn_h, *p_W0_h, *p_gruk_h, *p_dW_h, *p_oW_h, *p_xc_h, *p_state_h, *p_y_h;
    cudaGetSymbolAddress((void**)&p_gpart, g_gpart);
    cudaGetSymbolAddress((void**)&p_ypart, g_ypart);
    cudaGetSymbolAddress((void**)&p_attn_h, g_attn_h);
    cudaGetSymbolAddress((void**)&p_W0_h, g_W0_h);
    cudaGetSymbolAddress((void**)&p_gruk_h, g_gruk_h);
    cudaGetSymbolAddress((void**)&p_dW_h, g_dW_h);
    cudaGetSymbolAddress((void**)&p_oW_h, g_oW_h);
    cudaGetSymbolAddress((void**)&p_xc_h, g_xc_h);
    cudaGetSymbolAddress((void**)&p_state_h, g_state_h);
    cudaGetSymbolAddress((void**)&p_y_h, g_y_h);

    const int smemScore = 4 * STG + 64 * 4 * 4;  // 56320
    const int smemPart  = 4 * STG;               // 55296
    const int smemLog   = 4 * STG;               // 55296
    const int HALF_V = VV / 2;                   // 16000
    const int HALF_N8 = HALF_V / 8;              // 2000 col-chunks per row

    static cudaStream_t s2 = nullptr;
    static cudaEvent_t evFork = nullptr, ev1 = nullptr, ev2a = nullptr, ev2b = nullptr;
    static bool init_done = false;
    if (!init_done) {
        cudaFuncSetAttribute(score_async, cudaFuncAttributeMaxDynamicSharedMemorySize, smemScore);
        cudaFuncSetAttribute(gemm_async_part, cudaFuncAttributeMaxDynamicSharedMemorySize, smemPart);
        cudaFuncSetAttribute(logits_async, cudaFuncAttributeMaxDynamicSharedMemorySize, smemLog);
        cudaStreamCreateWithFlags(&s2, cudaStreamNonBlocking);
        cudaEventCreateWithFlags(&evFork, cudaEventDisableTiming);
        cudaEventCreateWithFlags(&ev1, cudaEventDisableTiming);
        cudaEventCreateWithFlags(&ev2a, cudaEventDisableTiming);
        cudaEventCreateWithFlags(&ev2b, cudaEventDisableTiming);
        init_done = true;
    }

    // 0a) fork side stream: oW cols [0,16000) -> ev2a; gru_k+dW -> ev1;
    //     oW cols [16000,32000) -> ev2b. Full grids (bandwidth machines).
    cudaEventRecord(evFork, 0);
    cudaStreamWaitEvent(s2, evFork, 0);
    f2h_cols<<<(UU * HALF_N8 + 255) / 256, 256, 0, s2>>>(oW, p_oW_h, VV, 0, HALF_N8);
    cudaEventRecord(ev2a, s2);
    f2h_dual<<<(2 * UU * 3 * UU / 8 + UU * UU / 8 + 255) / 256, 256, 0, s2>>>(
        gru_k, p_gruk_h, 2 * UU * 3 * UU / 8, dW, p_dW_h, UU * UU / 8);
    cudaEventRecord(ev1, s2);
    f2h_cols<<<(UU * HALF_N8 + 255) / 256, 256, 0, s2>>>(oW, p_oW_h, VV, HALF_V, HALF_N8);
    cudaEventRecord(ev2b, s2);

    // 0b) attn + W0 conversions (critical path, full grid)
    f2h_dual<<<(MM1 * UU / 8 + UU * UU / 8 + 255) / 256, 256>>>(
        attn, p_attn_h, MM1 * UU / 8, W0, p_W0_h, UU * UU / 8);

    // 1) attention score partials: cp.async pipeline, grid (128, 4)
    score_async<<<dim3(MM1 / 64, 4), 256, smemScore>>>(p_attn_h, p_W0_h, b0, b1, vW);
    // 2) combine partials + softmax + context + fp16 concat (+ alpha output)
    ctx_kernel<<<BB, 128>>>(attn, emb, inputs, vb, out_alpha);

    // 3) gates split-K(4): xc_h[128,1024] @ gru_k_h[1024,1536], grid (12,2,4)
    cudaStreamWaitEvent(0, ev1, 0);
    gemm_async_part<<<dim3(3 * UU / 128, BB / 64, 4), 256, smemPart>>>(
        p_xc_h, 2 * UU, p_gruk_h, 3 * UU, p_gpart, 2 * UU / 4);
    // 4) GRU nonlinearity + gates reduce (+ state output)
    gru_kernel<<<BB * UU / 4 / 256, 256>>>(gru_b, out_state);
    // 5) dense split-K(4): state_h[128,512] @ dW_h[512,512], grid (4,2,4)
    gemm_async_part<<<dim3(UU / 128, BB / 64, 4), 256, smemPart>>>(
        p_state_h, UU, p_dW_h, UU, p_ypart, UU / 4);
    // 5b) dense reduce + bias + relu -> fp16 y
    dense_reduce<<<BB * UU / 4 / 256, 256>>>(db);

    // 6) logits in two N-halves: half 1 joins ev2a, half 2 joins ev2b
    cudaStreamWaitEvent(0, ev2a, 0);
    logits_async<<<dim3(HALF_V / 128, BB / 64), 256, smemLog>>>(p_y_h, p_oW_h, ob,
                                                                out_logits, 0);
    cudaStreamWaitEvent(0, ev2b, 0);
    logits_async<<<dim3(HALF_V / 128, BB / 64), 256, smemLog>>>(p_y_h, p_oW_h, ob,
                                                                out_logits, HALF_V);
}